// round 5
// baseline (speedup 1.0000x reference)
#include <cuda_runtime.h>
#include <cuda_fp16.h>
#include <math.h>

#define DD  128
#define HW  16384            // 128*128
#define VOL 2097152          // 128^3
#define HVOL 1048576         // VOL/2
#define TY  16               // y-tile for fused blurYX

struct __align__(16) h4p { __half2 a, b, c, d; };  // pair of (z,y,x,pad)
struct __align__(8)  h2p { __half2 v0, v1; };      // pair of (img,lab)
struct __align__(8)  h4  { __half2 a, b; };

// ---- scratch (static device globals, allocation-free) ----
__device__ h4p     g_noisep[VOL];     // 32 MB paired noise/128
__device__ h4p     g_tmpFp[VOL];      // 32 MB paired warp(Ieps, AB)
__device__ h4p     g_tmpBp[VOL];      // 32 MB paired warp(Ieps, BA)
__device__ h2p     g_A2p[VOL];        // 16 MB paired (imgA, labA)
__device__ h2p     g_B2p[VOL];        // 16 MB paired (imgB, labB)
__device__ __half  g_WAh[VOL];        //  4 MB warp(imgA, AB)
__device__ __half  g_WBh[VOL];        //  4 MB warp(imgB, BA)
__device__ __half2 g_I2[VOL];         //  8 MB (imgA, imgB)
__device__ __half  g_blur[10 * VOL];  // 40 MB z-blurred channels
__device__ double  g_acc[16];

__constant__ float c_gk[5] = {
    0.05448868454964294f, 0.24420134200323332f, 0.40261995089424437f,
    0.24420134200323332f, 0.05448868454964294f };

__device__ __forceinline__ float idgv(int v) { return -1.0f + (float)v * (2.0f / 127.0f); }

__device__ __forceinline__ void axis_prep(float c, float& w0, float& w1, int& i0, int& i1) {
    float f  = floorf(c);
    float fr = c - f;
    int j0 = (int)f;
    w0 = (j0 >= 0 && j0 < DD)       ? (1.0f - fr) : 0.0f;
    w1 = (j0 >= -1 && j0 <= DD - 2) ? fr          : 0.0f;
    i0 = min(max(j0, 0), DD - 1);
    i1 = min(max(j0 + 1, 0), DD - 1);
}

__device__ __forceinline__ void axis_prep_pair(float c, float& pw0, float& pw1, int& base) {
    float f  = floorf(c);
    float fr = c - f;
    int j0 = (int)f;
    float w0 = (j0 >= 0 && j0 < DD)       ? (1.0f - fr) : 0.0f;
    float w1 = (j0 >= -1 && j0 <= DD - 2) ? fr          : 0.0f;
    if (j0 < 0) { pw0 = w1; pw1 = 0.0f; }
    else        { pw0 = w0; pw1 = w1;  }
    base = min(max(j0, 0), DD - 1);
}

struct Axes {
    float wz[2], wy[2];
    int   iz[2], iy[2];
    float pwx0, pwx1;
    int   ixb;
};

__device__ __forceinline__ Axes make_axes(const float* __restrict__ phi, int i) {
    Axes a;
    float z = (phi[i]           + 1.0f) * 63.5f;
    float y = (phi[VOL + i]     + 1.0f) * 63.5f;
    float x = (phi[2 * VOL + i] + 1.0f) * 63.5f;
    axis_prep(z, a.wz[0], a.wz[1], a.iz[0], a.iz[1]);
    axis_prep(y, a.wy[0], a.wy[1], a.iy[0], a.iy[1]);
    axis_prep_pair(x, a.pwx0, a.pwx1, a.ixb);
    return a;
}

__device__ __forceinline__ float3 gather_h4p(const h4p* __restrict__ src, const Axes& a) {
    float a0 = 0.f, a1 = 0.f, a2 = 0.f;
#pragma unroll
    for (int dz = 0; dz < 2; dz++) {
        int rz = a.iz[dz] * HW;
#pragma unroll
        for (int dy = 0; dy < 2; dy++) {
            float wzy = a.wz[dz] * a.wy[dy];
            float w0 = wzy * a.pwx0, w1 = wzy * a.pwx1;
            h4p v = src[rz + a.iy[dy] * DD + a.ixb];
            float2 p0 = __half22float2(v.a);
            float  q0 = __half2float(v.b.x);
            float2 p1 = __half22float2(v.c);
            float  q1 = __half2float(v.d.x);
            a0 += w0 * p0.x + w1 * p1.x;
            a1 += w0 * p0.y + w1 * p1.y;
            a2 += w0 * q0   + w1 * q1;
        }
    }
    return make_float3(a0, a1, a2);
}

__device__ __forceinline__ float2 gather_h2p(const h2p* __restrict__ src, const Axes& a) {
    float a0 = 0.f, a1 = 0.f;
#pragma unroll
    for (int dz = 0; dz < 2; dz++) {
        int rz = a.iz[dz] * HW;
#pragma unroll
        for (int dy = 0; dy < 2; dy++) {
            float wzy = a.wz[dz] * a.wy[dy];
            float w0 = wzy * a.pwx0, w1 = wzy * a.pwx1;
            h2p v = src[rz + a.iy[dy] * DD + a.ixb];
            float2 p0 = __half22float2(v.v0);
            float2 p1 = __half22float2(v.v1);
            a0 += w0 * p0.x + w1 * p1.x;
            a1 += w0 * p0.y + w1 * p1.y;
        }
    }
    return make_float2(a0, a1);
}

__device__ __forceinline__ float3 warp_idg(const Axes& a) {
    float Sz0 = a.wz[0] + a.wz[1];
    float Sy0 = a.wy[0] + a.wy[1];
    float Sx0 = a.pwx0 + a.pwx1;
    float Sz1 = a.wz[0] * idgv(a.iz[0]) + a.wz[1] * idgv(a.iz[1]);
    float Sy1 = a.wy[0] * idgv(a.iy[0]) + a.wy[1] * idgv(a.iy[1]);
    float Sx1 = a.pwx0 * idgv(a.ixb) + a.pwx1 * idgv(min(a.ixb + 1, DD - 1));
    return make_float3(Sz1 * Sy0 * Sx0, Sz0 * Sy1 * Sx0, Sz0 * Sy0 * Sx1);
}

__device__ __forceinline__ void block_add(double v, double* dst) {
    __shared__ double sm[8];
    int lane = threadIdx.x & 31;
    int wid  = threadIdx.x >> 5;
#pragma unroll
    for (int o = 16; o > 0; o >>= 1) v += __shfl_down_sync(0xffffffffu, v, o);
    __syncthreads();
    if (lane == 0) sm[wid] = v;
    __syncthreads();
    if (wid == 0) {
        double t = (lane < 8) ? sm[lane] : 0.0;
#pragma unroll
        for (int o = 4; o > 0; o >>= 1) t += __shfl_down_sync(0xffffffffu, t, o);
        if (lane == 0) atomicAdd(dst, t);
    }
}

__global__ void k_init() {
    if (threadIdx.x < 16) g_acc[threadIdx.x] = 0.0;
}

__global__ void k_pack(const float* __restrict__ noise,
                       const float* __restrict__ imgA, const float* __restrict__ labA,
                       const float* __restrict__ imgB, const float* __restrict__ labB) {
    int i = blockIdx.x * 256 + threadIdx.x;
    int x = i & 127;
    int j = (x < 127) ? i + 1 : i;

    h4p n;
    n.a = __floats2half2_rn(noise[i] * (1.0f/128.0f), noise[VOL + i] * (1.0f/128.0f));
    n.b = __floats2half2_rn(noise[2*VOL + i] * (1.0f/128.0f), 0.0f);
    n.c = __floats2half2_rn(noise[j] * (1.0f/128.0f), noise[VOL + j] * (1.0f/128.0f));
    n.d = __floats2half2_rn(noise[2*VOL + j] * (1.0f/128.0f), 0.0f);
    g_noisep[i] = n;

    float la = labA[i], lb = labB[i];
    h2p pa, pb;
    pa.v0 = __floats2half2_rn(imgA[i], la);
    pa.v1 = __floats2half2_rn(imgA[j], labA[j]);
    pb.v0 = __floats2half2_rn(imgB[i], lb);
    pb.v1 = __floats2half2_rn(imgB[j], labB[j]);
    g_A2p[i] = pa;
    g_B2p[i] = pb;
    g_I2[i]  = __floats2half2_rn(imgA[i], imgB[i]);

    block_add((double)lb, &g_acc[3]);
    block_add((double)la, &g_acc[6]);
}

// one direction: inner Ieps warp + (img,lab) warp + dice numerator sums. 2 vox/thread.
__global__ void k_warp_dir(const float* __restrict__ phi, const h2p* __restrict__ src2,
                           const float* __restrict__ othlab,
                           h4p* __restrict__ tmpdst, __half* __restrict__ wdst, int acc0) {
    __shared__ h4 buf[2][256];
    int tid = threadIdx.x;
    int i0 = blockIdx.x * 256 + tid;
    int i1 = i0 + HVOL;

    Axes a0 = make_axes(phi, i0);
    Axes a1 = make_axes(phi, i1);
    float3 gI0 = warp_idg(a0);
    float3 gI1 = warp_idg(a1);
    float3 n0 = gather_h4p(g_noisep, a0);
    float3 n1 = gather_h4p(g_noisep, a1);
    float2 w0 = gather_h2p(src2, a0);
    float2 w1 = gather_h2p(src2, a1);

    buf[0][tid].a = __floats2half2_rn(gI0.x + n0.x, gI0.y + n0.y);
    buf[0][tid].b = __floats2half2_rn(gI0.z + n0.z, 0.0f);
    buf[1][tid].a = __floats2half2_rn(gI1.x + n1.x, gI1.y + n1.y);
    buf[1][tid].b = __floats2half2_rn(gI1.z + n1.z, 0.0f);
    __syncthreads();
    int dn = ((tid & 127) < 127) ? 1 : 0;
    {
        h4p o;
        o.a = buf[0][tid].a;      o.b = buf[0][tid].b;
        o.c = buf[0][tid + dn].a; o.d = buf[0][tid + dn].b;
        tmpdst[i0] = o;
        h4p p;
        p.a = buf[1][tid].a;      p.b = buf[1][tid].b;
        p.c = buf[1][tid + dn].a; p.d = buf[1][tid + dn].b;
        tmpdst[i1] = p;
    }
    wdst[i0] = __float2half_rn(w0.x);
    wdst[i1] = __float2half_rn(w1.x);

    double prod = (double)(w0.y * othlab[i0]) + (double)(w1.y * othlab[i1]);
    double wsum = (double)w0.y + (double)w1.y;
    block_add(prod, &g_acc[acc0]);
    block_add(wsum, &g_acc[acc0 + 1]);
}

// one direction of MSE: acc[0] += |Ieps - warp(tmp, phi)|^2. 2 vox/thread.
__global__ void k_mse_dir(const float* __restrict__ phi, const h4p* __restrict__ tmp) {
    int tid = threadIdx.x;
    int i0 = blockIdx.x * 256 + tid;
    int i1 = i0 + HVOL;
    Axes a0 = make_axes(phi, i0);
    Axes a1 = make_axes(phi, i1);
    float3 f0 = gather_h4p(tmp, a0);
    float3 f1 = gather_h4p(tmp, a1);

    h4p nh0 = g_noisep[i0];
    h4p nh1 = g_noisep[i1];
    float2 m0 = __half22float2(nh0.a); float q0 = __half2float(nh0.b.x);
    float2 m1 = __half22float2(nh1.a); float q1 = __half2float(nh1.b.x);

    int z0 = i0 >> 14, y0 = (i0 >> 7) & 127, x0 = i0 & 127;
    int z1 = i1 >> 14, y1 = (i1 >> 7) & 127, x1 = i1 & 127;
    float e00 = idgv(z0) + m0.x, e01 = idgv(y0) + m0.y, e02 = idgv(x0) + q0;
    float e10 = idgv(z1) + m1.x, e11 = idgv(y1) + m1.y, e12 = idgv(x1) + q1;

    float d0 = e00 - f0.x, d1 = e01 - f0.y, d2 = e02 - f0.z;
    float c0 = e10 - f1.x, c1 = e11 - f1.y, c2 = e12 - f1.z;
    double s = (double)(d0*d0) + (double)(d1*d1) + (double)(d2*d2)
             + (double)(c0*c0) + (double)(c1*c1) + (double)(c2*c2);
    block_add(s, &g_acc[0]);
}

__global__ void k_blurZ10() {
    int i = blockIdx.x * 256 + threadIdx.x;
    int z = i >> 14;
    float a[10];
#pragma unroll
    for (int c = 0; c < 10; c++) a[c] = 0.f;
#pragma unroll
    for (int t = 0; t < 5; t++) {
        int zz = z + t - 2;
        if ((unsigned)zz < (unsigned)DD) {
            int off = i + (t - 2) * HW;
            float k = c_gk[t];
            float wa = __half2float(g_WAh[off]);
            float wb = __half2float(g_WBh[off]);
            float2 ij = __half22float2(g_I2[off]);
            float ia = ij.x, jb = ij.y;
            a[0] += k * wa;      a[1] += k * jb;
            a[2] += k * wa * jb; a[3] += k * wa * wa; a[4] += k * jb * jb;
            a[5] += k * ia;      a[6] += k * wb;
            a[7] += k * ia * wb; a[8] += k * ia * ia; a[9] += k * wb * wb;
        }
    }
#pragma unroll
    for (int c = 0; c < 10; c++) g_blur[c * VOL + i] = __float2half_rn(a[c]);
}

__global__ void k_blurYX_red() {
    extern __shared__ char smraw[];
    __half* sin_ = (__half*)smraw;
    float*  srow = (float*)(smraw + 10 * (TY + 4) * 128 * 2);

    int tid = threadIdx.x;
    int z   = blockIdx.x >> 3;
    int y0  = (blockIdx.x & 7) * TY;

    uint2*       s4 = (uint2*)smraw;
    const uint2* gb = (const uint2*)&g_blur[0];
    const int units_per_ch = (TY + 4) * 32;
    for (int u = tid; u < 10 * units_per_ch; u += 256) {
        int c   = u / units_per_ch;
        int rem = u - c * units_per_ch;
        int r   = rem >> 5;
        int xu  = rem & 31;
        int y   = y0 + r - 2;
        uint2 v = make_uint2(0u, 0u);
        if ((unsigned)y < (unsigned)DD)
            v = gb[((c * VOL + ((z << 7) + y) * DD) >> 2) + xu];
        s4[u] = v;
    }
    __syncthreads();

    int half_ = tid >> 7;
    int x     = tid & 127;
    double local = 0.0;

#pragma unroll 1
    for (int it = 0; it < TY / 2; it++) {
        int ry = it * 2 + half_;
        float val[10];
#pragma unroll
        for (int c = 0; c < 10; c++) val[c] = 0.f;
#pragma unroll
        for (int t = 0; t < 5; t++) {
            float k = c_gk[t];
            int r = ry + t;
#pragma unroll
            for (int c = 0; c < 10; c++)
                val[c] += k * __half2float(sin_[c * (TY + 4) * 128 + r * 128 + x]);
        }
#pragma unroll
        for (int c = 0; c < 10; c++) srow[c * 256 + half_ * 128 + x] = val[c];
        __syncthreads();

        float v[10];
#pragma unroll
        for (int c = 0; c < 10; c++) v[c] = 0.f;
#pragma unroll
        for (int t = 0; t < 5; t++) {
            int xx = x + t - 2;
            if ((unsigned)xx < (unsigned)DD) {
                float k = c_gk[t];
#pragma unroll
                for (int c = 0; c < 10; c++)
                    v[c] += k * srow[c * 256 + half_ * 128 + xx];
            }
        }
        float cr1 = v[2] - v[0] * v[1];
        float vI1 = fmaxf(v[3] - v[0] * v[0], 0.f) + 1e-5f;
        float vJ1 = fmaxf(v[4] - v[1] * v[1], 0.f) + 1e-5f;
        float cr2 = v[7] - v[5] * v[6];
        float vI2 = fmaxf(v[8] - v[5] * v[5], 0.f) + 1e-5f;
        float vJ2 = fmaxf(v[9] - v[6] * v[6], 0.f) + 1e-5f;
        local += (double)(1.0f - cr1 * rsqrtf(vI1 * vJ1))
               + (double)(1.0f - cr2 * rsqrtf(vI2 * vJ2));
        __syncthreads();
    }
    block_add(local, &g_acc[7]);
}

__global__ void k_final(float* __restrict__ out) {
    double ic    = g_acc[0] / (3.0 * (double)VOL);
    double dice1 = (2.0 * g_acc[1] + 1e-5) / (g_acc[2] + g_acc[3] + 1e-5);
    double dice2 = (2.0 * g_acc[4] + 1e-5) / (g_acc[5] + g_acc[6] + 1e-5);
    double dl    = (1.0 - dice1) + (1.0 - dice2);
    double sim   = g_acc[7] / (double)VOL;
    out[0] = (float)(128.0 * ic + sim + dl);
}

extern "C" void kernel_launch(void* const* d_in, const int* in_sizes, int n_in,
                              void* d_out, int out_size) {
    const float* phiAB = (const float*)d_in[0];
    const float* phiBA = (const float*)d_in[1];
    const float* imgA  = (const float*)d_in[2];
    const float* imgB  = (const float*)d_in[3];
    const float* labA  = (const float*)d_in[4];
    const float* labB  = (const float*)d_in[5];
    const float* noise = (const float*)d_in[6];
    float* out = (float*)d_out;

    // one-time infra (streams/events are not device-memory allocations)
    static cudaStream_t s1 = nullptr;
    static cudaEvent_t evPack, evAB, evBA, evZ;
    if (s1 == nullptr) {
        cudaStreamCreateWithFlags(&s1, cudaStreamNonBlocking);
        cudaEventCreateWithFlags(&evPack, cudaEventDisableTiming);
        cudaEventCreateWithFlags(&evAB,   cudaEventDisableTiming);
        cudaEventCreateWithFlags(&evBA,   cudaEventDisableTiming);
        cudaEventCreateWithFlags(&evZ,    cudaEventDisableTiming);
    }

    h4p *pTmpF = nullptr, *pTmpB = nullptr;
    h2p *pA2p = nullptr, *pB2p = nullptr;
    __half *pWA = nullptr, *pWB = nullptr;
    cudaGetSymbolAddress((void**)&pTmpF, g_tmpFp);
    cudaGetSymbolAddress((void**)&pTmpB, g_tmpBp);
    cudaGetSymbolAddress((void**)&pA2p, g_A2p);
    cudaGetSymbolAddress((void**)&pB2p, g_B2p);
    cudaGetSymbolAddress((void**)&pWA, g_WAh);
    cudaGetSymbolAddress((void**)&pWB, g_WBh);

    const int smem_yx = 10 * (TY + 4) * 128 * 2 + 10 * 2 * 128 * 4;  // 61,440 B
    cudaFuncSetAttribute(k_blurYX_red,
                         cudaFuncAttributeMaxDynamicSharedMemorySize, smem_yx);

    // stream 0: init, pack, warp_AB, mse_fwd, mse_bwd, blurYX, final
    // stream 1: warp_BA, blurZ
    k_init<<<1, 32>>>();
    k_pack<<<VOL / 256, 256>>>(noise, imgA, labA, imgB, labB);
    cudaEventRecord(evPack, 0);
    cudaStreamWaitEvent(s1, evPack, 0);

    k_warp_dir<<<VOL / 512, 256>>>(phiAB, pA2p, labB, pTmpF, pWA, 1);
    cudaEventRecord(evAB, 0);
    k_warp_dir<<<VOL / 512, 256, 0, s1>>>(phiBA, pB2p, labA, pTmpB, pWB, 4);
    cudaEventRecord(evBA, s1);

    k_mse_dir<<<VOL / 512, 256>>>(phiBA, pTmpF);       // fwd: warp(tmpF, BA)
    cudaStreamWaitEvent(0, evBA, 0);
    k_mse_dir<<<VOL / 512, 256>>>(phiAB, pTmpB);       // bwd: warp(tmpB, AB)

    cudaStreamWaitEvent(s1, evAB, 0);                  // blurZ needs WA too
    k_blurZ10<<<VOL / 256, 256, 0, s1>>>();
    cudaEventRecord(evZ, s1);

    cudaStreamWaitEvent(0, evZ, 0);                    // join s1
    k_blurYX_red<<<1024, 256, smem_yx>>>();
    k_final<<<1, 1>>>(out);
}